// round 13
// baseline (speedup 1.0000x reference)
#include <cuda_runtime.h>

#define EPS 1e-4f
constexpr int IN_DIM = 30;
constexpr int D1 = 20;
constexpr int D2 = 15;
constexpr int WPB = 4;          // warps per block; each warp: 2 matrices
constexpr int SCRN = 1536;      // floats of scratch per warp
constexpr int KU = 4;           // rounds per unrolled chunk
constexpr int IT1 = 24;         // 96 rounds ~ 5 sweeps (20x20)
constexpr int IT2 = 19;         // 76 rounds ~ 5 sweeps (16x16)
constexpr unsigned FULL = 0xffffffffu;

// Tournament migration: NEW[l] = OLD[sigma(l)]. Position 0 fixed.
__host__ __device__ constexpr int sigma(int N, int l) {
    if (l >= N) return l;
    if (l == 0) return 0;
    if (l == N - 1) return N - 2;
    if (l & 1) return l + 2;   // odd slots move down the ring
    if (l == 2) return 1;
    return l - 2;              // even slots >= 4
}

// sigma applied j times (compile-time foldable)
__host__ __device__ constexpr int sigpow(int N, int j, int i) {
    int x = i;
    for (int t = 0; t < j; ++t) x = sigma(N, x);
    return x;
}

// One Jacobi round at unroll step J: positions are addressed at register
// sigpow(J, pos); lane-side migration is an in-place shuffle; register-side
// migration is absorbed into the naming of step J+1.
template <int N, int W, int J>
__device__ __forceinline__ void jacobi_round(float* a, float* vt, float& dg,
                                             int llane, int sig, int role,
                                             int myk, int kk, float* rb) {
    constexpr int buf = J & 1;
    float d_oth = __shfl_xor_sync(FULL, dg, 1);
    // --- even pair-lane computes rotation, publishes via shared ---
    if (!role && llane < N) {
        float off = 0.0f;
        #pragma unroll
        for (int k = 0; k < N / 2; ++k)
            if (myk == k) off = a[sigpow(N, J, 2 * k + 1)];   // A[q][p]
        float c = 1.0f, s = 0.0f, t = 0.0f;
        if (fabsf(off) > 1e-30f) {
            float tau = (d_oth - dg) / (2.0f * off);
            t = copysignf(1.0f, tau) /
                (fabsf(tau) + sqrtf(fmaf(tau, tau, 1.0f)));
            c = rsqrtf(fmaf(t, t, 1.0f));
            s = t * c;
        }
        reinterpret_cast<float2*>(rb + buf * N)[myk] = make_float2(c, s);
        rb[2 * N + buf * (N / 2) + myk] = fmaf(t, off, d_oth); // odd diag'
        dg = fmaf(-t, off, dg);                                // even diag'
    }
    __syncwarp();
    // --- own-pair coefficients (LDS.64; broadcast within pair) ---
    float2 mycs = reinterpret_cast<const float2*>(rb + buf * N)[kk];
    float c = mycs.x, s = mycs.y;
    if (role) dg = rb[2 * N + buf * (N / 2) + kk];
    // --- column phase: applies to every row -> every register directly ---
    float sg = role ? s : -s;
    #pragma unroll
    for (int i = 0; i < N; ++i) {
        float o = __shfl_xor_sync(FULL, a[i], 1);
        a[i] = fmaf(c, a[i], sg * o);
    }
    // --- row phase: positions (4k..4k+3) at composed register indices ---
    const float4* csv = reinterpret_cast<const float4*>(rb + buf * N);
    #pragma unroll
    for (int k4 = 0; k4 < N / 4; ++k4) {
        float4 q = csv[k4];
        {
            float ck = q.x, sk = q.y;
            const int r0 = sigpow(N, J, 4 * k4 + 0);
            const int r1 = sigpow(N, J, 4 * k4 + 1);
            float ae = a[r0], ao = a[r1];
            a[r0] = fmaf(ck, ae, -sk * ao);
            a[r1] = fmaf(sk, ae,  ck * ao);
            float ve = vt[r0], vo = vt[r1];
            vt[r0] = fmaf(ck, ve, -sk * vo);
            vt[r1] = fmaf(sk, ve,  ck * vo);
        }
        {
            float ck = q.z, sk = q.w;
            const int r2 = sigpow(N, J, 4 * k4 + 2);
            const int r3 = sigpow(N, J, 4 * k4 + 3);
            float ae = a[r2], ao = a[r3];
            a[r2] = fmaf(ck, ae, -sk * ao);
            a[r3] = fmaf(sk, ae,  ck * ao);
            float ve = vt[r2], vo = vt[r3];
            vt[r2] = fmaf(ck, ve, -sk * vo);
            vt[r3] = fmaf(sk, ve,  ck * vo);
        }
    }
    // --- migration, lane side only (register side absorbed by naming) ---
    #pragma unroll
    for (int i = 0; i < N; ++i) a[i] = __shfl_sync(FULL, a[i], sig, W);
    dg = __shfl_sync(FULL, dg, sig, W);
}

// iters chunks of KU rounds; bottom of each chunk restores canonical naming.
template <int N, int W>
__device__ __forceinline__ void jacobi_smem(float* a, float* vt, float& dg,
                                            int llane, int sig, int iters,
                                            float* rb) {
    const int role = llane & 1;
    const int myk = llane >> 1;
    const int kk = (myk < N / 2) ? myk : 0;
    #pragma unroll 1
    for (int it = 0; it < iters; ++it) {
        jacobi_round<N, W, 0>(a, vt, dg, llane, sig, role, myk, kk, rb);
        jacobi_round<N, W, 1>(a, vt, dg, llane, sig, role, myk, kk, rb);
        jacobi_round<N, W, 2>(a, vt, dg, llane, sig, role, myk, kk, rb);
        jacobi_round<N, W, 3>(a, vt, dg, llane, sig, role, myk, kk, rb);
        float tmp[N];
        #pragma unroll
        for (int i = 0; i < N; ++i) tmp[i] = a[sigpow(N, KU, i)];
        #pragma unroll
        for (int i = 0; i < N; ++i) a[i] = tmp[i];
        #pragma unroll
        for (int i = 0; i < N; ++i) tmp[i] = vt[sigpow(N, KU, i)];
        #pragma unroll
        for (int i = 0; i < N; ++i) vt[i] = tmp[i];
    }
}

__global__ __launch_bounds__(WPB * 32, 7)
void spdnet_kernel(const float* __restrict__ Xg,
                   const float* __restrict__ W1g,
                   const float* __restrict__ W2g,
                   float* __restrict__ out, int nb) {
    __shared__ float W1s[D1 * IN_DIM];           // 20x30
    __shared__ float W2s[D2 * D1];               // 15x20
    __shared__ __align__(16) float scr_all[WPB][SCRN];

    int tid = threadIdx.x, warp = tid >> 5, lane = tid & 31;
    for (int i = tid; i < D1 * IN_DIM; i += WPB * 32) W1s[i] = W1g[i];
    for (int i = tid; i < D2 * D1;    i += WPB * 32) W2s[i] = W2g[i];
    __syncthreads();

    int npairs = (nb + 1) >> 1;
    int wm = blockIdx.x * WPB + warp;
    if (wm >= npairs) return;      // warp-uniform; only warp-level sync below
    float* scr = scr_all[warp];

    // ============ stage 1 twice; park A2 columns (+diag) at scr[960+] =====
    #pragma unroll 1
    for (int h = 0; h < 2; ++h) {
        int m = 2 * wm + h; if (m >= nb) m = nb - 1;

        // ---- load X (pitch 32), pad, symmetrize ----
        {
            const float* xg = Xg + (size_t)m * 900;
            for (int e = lane; e < 900; e += 32) {
                int i = e / 30, k = e - i * 30;
                scr[i * 32 + k] = xg[e];
            }
            for (int e = lane; e < 60; e += 32)
                scr[(e >> 1) * 32 + 30 + (e & 1)] = 0.0f;
        }
        __syncwarp();
        for (int e = lane; e < 900; e += 32) {
            int i = e / 30, k = e - i * 30;
            if (i < k) {
                float v = 0.5f * (scr[i * 32 + k] + scr[k * 32 + i]);
                scr[i * 32 + k] = v; scr[k * 32 + i] = v;
            }
        }
        __syncwarp();

        // ---- bimap1: A = W1 * Xs * W1^T + EPS*I (column per lane) ----
        float a[D1], vt[D1], dg = 1.0f;
        #pragma unroll
        for (int i = 0; i < D1; ++i) { a[i] = 0.0f; vt[i] = 0.0f; }
        if (lane < D1) {
            float wreg[32];
            #pragma unroll
            for (int k = 0; k < IN_DIM; ++k) wreg[k] = W1s[lane * IN_DIM + k];
            wreg[30] = 0.0f; wreg[31] = 0.0f;
            float t[IN_DIM];
            for (int i = 0; i < IN_DIM; ++i) {
                const float4* x4 = reinterpret_cast<const float4*>(&scr[i * 32]);
                float acc = 0.0f;
                #pragma unroll
                for (int q = 0; q < 8; ++q) {
                    float4 x = x4[q];
                    acc = fmaf(x.x, wreg[4 * q + 0], acc);
                    acc = fmaf(x.y, wreg[4 * q + 1], acc);
                    acc = fmaf(x.z, wreg[4 * q + 2], acc);
                    acc = fmaf(x.w, wreg[4 * q + 3], acc);
                }
                t[i] = acc;
            }
            #pragma unroll
            for (int r = 0; r < D1; ++r) {
                float acc = 0.0f;
                #pragma unroll
                for (int i = 0; i < IN_DIM; ++i)
                    acc = fmaf(W1s[r * IN_DIM + i], t[i], acc);
                a[r] = acc;
                if (r == lane) { a[r] += EPS; dg = a[r]; }
            }
            #pragma unroll
            for (int k = 0; k < D1; ++k) vt[k] = (k == lane) ? 1.0f : 0.0f;
        }
        __syncwarp();

        // ---- eigensolve 20x20 (rb at scr+896; X area dead now) ----
        jacobi_smem<D1, 32>(a, vt, dg, lane, sigma(D1, lane), IT1, scr + 896);

        // ---- fused reeig + bimap2: A2 = Z Z^T + EPS*I, Z = W2*(V*sqrt) ----
        float g = sqrtf(fmaxf(dg, EPS));
        #pragma unroll
        for (int k = 0; k < D1; ++k) {
            float rk = __shfl_sync(FULL, g, k);
            vt[k] *= rk;
        }
        if (lane < D1) {
            #pragma unroll
            for (int k = 0; k < D1; ++k) scr[lane * 24 + k] = vt[k]; // Vs p24
        }
        __syncwarp();
        float z[D1];
        #pragma unroll
        for (int k = 0; k < D1; ++k) z[k] = 0.0f;
        if (lane < D2) {
            float w2r[D1];
            #pragma unroll
            for (int r = 0; r < D1; ++r) w2r[r] = W2s[lane * D1 + r];
            for (int r = 0; r < D1; ++r) {
                const float4* v4 = reinterpret_cast<const float4*>(&scr[r * 24]);
                float w = w2r[r];
                #pragma unroll
                for (int q = 0; q < 5; ++q) {
                    float4 x = v4[q];
                    z[4 * q + 0] = fmaf(w, x.x, z[4 * q + 0]);
                    z[4 * q + 1] = fmaf(w, x.y, z[4 * q + 1]);
                    z[4 * q + 2] = fmaf(w, x.z, z[4 * q + 2]);
                    z[4 * q + 3] = fmaf(w, x.w, z[4 * q + 3]);
                }
            }
        }
        __syncwarp();
        if (lane < D2) {
            #pragma unroll
            for (int k = 0; k < D1; ++k) scr[480 + lane * 24 + k] = z[k]; // Zs
        }
        __syncwarp();

        if (lane < 16) {
            float a2[16];
            #pragma unroll
            for (int b = 0; b < D2; ++b) {        // A2[b][lane] = Zrow_b . z
                const float4* zb = reinterpret_cast<const float4*>(&scr[480 + b * 24]);
                float acc = 0.0f;
                #pragma unroll
                for (int q = 0; q < 5; ++q) {
                    float4 x = zb[q];
                    acc = fmaf(x.x, z[4 * q + 0], acc);
                    acc = fmaf(x.y, z[4 * q + 1], acc);
                    acc = fmaf(x.z, z[4 * q + 2], acc);
                    acc = fmaf(x.w, z[4 * q + 3], acc);
                }
                a2[b] = acc;
            }
            a2[15] = 0.0f;                        // padded dim decoupled
            a2[lane] += EPS;
            float4* dst = reinterpret_cast<float4*>(&scr[960 + h * 272 + lane * 16]);
            const float4* src = reinterpret_cast<const float4*>(a2);
            #pragma unroll
            for (int q = 0; q < 4; ++q) dst[q] = src[q];
            scr[960 + h * 272 + 256 + lane] = a2[lane];
        }
        __syncwarp();
    }

    // ====== dual 16x16 eigensolve: lanes 0-15 mat 0, lanes 16-31 mat 1 =====
    int g2 = lane >> 4, llane = lane & 15;
    float A2[16], vt2[16];
    {
        const float4* src = reinterpret_cast<const float4*>(&scr[960 + g2 * 272 + llane * 16]);
        float4* dst = reinterpret_cast<float4*>(A2);
        #pragma unroll
        for (int q = 0; q < 4; ++q) dst[q] = src[q];
    }
    float dg2 = scr[960 + g2 * 272 + 256 + llane];
    #pragma unroll
    for (int k = 0; k < 16; ++k) vt2[k] = (k == llane) ? 1.0f : 0.0f;
    __syncwarp();

    // rb for the two groups at scr[0..96) (Vs/Zs dead)
    jacobi_smem<16, 16>(A2, vt2, dg2, llane, sigma(16, llane), IT2,
                        scr + g2 * 48);

    // ============== logeig recompose (per group), triangle output =========
    float lw = logf(fmaxf(dg2, EPS));
    __syncwarp();   // rb reads done before recompose overwrites scr[0..96)
    #pragma unroll
    for (int k = 0; k < 16; ++k) {
        float lwk = __shfl_sync(FULL, lw, k, 16);
        float raw = vt2[k];
        if (llane < D2) {
            scr[g2 * 512 + llane * 16 + k]       = raw;        // raw rows
            scr[g2 * 512 + 256 + llane * 16 + k] = raw * lwk;  // scaled rows
        }
    }
    __syncwarp();

    int m = 2 * wm + g2;
    if (m < nb) {
        const float* base = &scr[g2 * 512];
        for (int tt = llane; tt < 120; tt += 16) {
            int i = 0, rem = tt;
            while (rem >= D2 - i) { rem -= D2 - i; ++i; }
            int j = i + rem;
            const float4* ri = reinterpret_cast<const float4*>(&base[256 + i * 16]);
            const float4* rj = reinterpret_cast<const float4*>(&base[j * 16]);
            float acc = 0.0f;
            #pragma unroll
            for (int q = 0; q < 4; ++q) {
                float4 x = ri[q], y = rj[q];
                acc = fmaf(x.x, y.x, fmaf(x.y, y.y, fmaf(x.z, y.z, fmaf(x.w, y.w, acc))));
            }
            out[(size_t)m * 120 + tt] = acc;
        }
    }
}

extern "C" void kernel_launch(void* const* d_in, const int* in_sizes, int n_in,
                              void* d_out, int out_size) {
    const float* X  = (const float*)d_in[0];
    const float* W1 = (const float*)d_in[1];
    const float* W2 = (const float*)d_in[2];
    float* out = (float*)d_out;
    int nb = in_sizes[0] / (IN_DIM * IN_DIM);
    int npairs = (nb + 1) / 2;
    int blocks = (npairs + WPB - 1) / WPB;
    spdnet_kernel<<<blocks, WPB * 32>>>(X, W1, W2, out, nb);
}

// round 15
// speedup vs baseline: 1.7133x; 1.7133x over previous
#include <cuda_runtime.h>

#define EPS 1e-4f
constexpr int IN_DIM = 30;
constexpr int D1 = 20;
constexpr int D2 = 15;
constexpr int WPB = 4;          // warps per block; each warp: 2 matrices
constexpr int IT1 = 48;         // 96 rounds (~5 sweeps of 20x20, 19/sweep)
constexpr int IT2 = 38;         // 76 rounds (~5 sweeps of 16x16, 15/sweep)
constexpr int SCRN = 1536;      // floats of scratch per warp
constexpr unsigned FULL = 0xffffffffu;

// Tournament migration: NEW[l] = OLD[sigma(l)]. Position 0 fixed.
__host__ __device__ constexpr int sigma(int N, int l) {
    if (l >= N) return l;
    if (l == 0) return 0;
    if (l == N - 1) return N - 2;
    if (l & 1) return l + 2;   // odd slots move down the ring
    if (l == 2) return 1;
    return l - 2;              // even slots >= 4
}

// vt register index for phase PH (0: canonical, 1: one migration deferred)
__host__ __device__ constexpr int vmap(int N, int PH, int i) {
    return PH ? sigma(N, i) : i;
}

// One Jacobi round. A registers stay canonical (migrated every round,
// register side folds into the SHFL). vt migration is DEFERRED on PH=0
// rounds; PH=1 rounds address vt through sigma and then restore with a
// single sigma^2 permutation. rb: cs[2][N/2 float2] at 0, diag[2][N/2]
// at 2N (double-buffered by PH).
template <int N, int W, int PH>
__device__ __forceinline__ void jround(float* a, float* vt, float& dg,
                                       int llane, int sig, int role,
                                       int myk, int kk, float* rb) {
    constexpr int buf = PH;
    float d_oth = __shfl_xor_sync(FULL, dg, 1);
    // --- even pair-lane computes rotation, publishes via shared ---
    if (!role && llane < N) {
        float off = 0.0f;
        #pragma unroll
        for (int k = 0; k < N / 2; ++k)
            if (myk == k) off = a[2 * k + 1];   // off-diag A[q][p]
        float c = 1.0f, s = 0.0f, t = 0.0f;
        if (fabsf(off) > 1e-30f) {
            float tau = (d_oth - dg) / (2.0f * off);
            t = copysignf(1.0f, tau) /
                (fabsf(tau) + sqrtf(fmaf(tau, tau, 1.0f)));
            c = rsqrtf(fmaf(t, t, 1.0f));
            s = t * c;
        }
        reinterpret_cast<float2*>(rb + buf * N)[myk] = make_float2(c, s);
        rb[2 * N + buf * (N / 2) + myk] = fmaf(t, off, d_oth); // odd diag'
        dg = fmaf(-t, off, dg);                                // even diag'
    }
    __syncwarp();
    // --- own-pair coefficients (LDS.64; broadcast within pair) ---
    float2 mycs = reinterpret_cast<const float2*>(rb + buf * N)[kk];
    float c = mycs.x, s = mycs.y;
    if (role) dg = rb[2 * N + buf * (N / 2) + kk];
    // --- column phase: A <- A*J (partner exchange via shfl_xor) ---
    float sg = role ? s : -s;
    #pragma unroll
    for (int i = 0; i < N; ++i) {
        float o = __shfl_xor_sync(FULL, a[i], 1);
        a[i] = fmaf(c, a[i], sg * o);
    }
    // --- row phase: A canonical indices; vt via vmap; cs via LDS.128 ---
    const float4* csv = reinterpret_cast<const float4*>(rb + buf * N);
    #pragma unroll
    for (int k4 = 0; k4 < N / 4; ++k4) {
        float4 q = csv[k4];
        {
            float ck = q.x, sk = q.y;
            float ae = a[4 * k4], ao = a[4 * k4 + 1];
            a[4 * k4]     = fmaf(ck, ae, -sk * ao);
            a[4 * k4 + 1] = fmaf(sk, ae,  ck * ao);
            const int v0 = vmap(N, PH, 4 * k4), v1 = vmap(N, PH, 4 * k4 + 1);
            float ve = vt[v0], vo = vt[v1];
            vt[v0] = fmaf(ck, ve, -sk * vo);
            vt[v1] = fmaf(sk, ve,  ck * vo);
        }
        {
            float ck = q.z, sk = q.w;
            float ae = a[4 * k4 + 2], ao = a[4 * k4 + 3];
            a[4 * k4 + 2] = fmaf(ck, ae, -sk * ao);
            a[4 * k4 + 3] = fmaf(sk, ae,  ck * ao);
            const int v2 = vmap(N, PH, 4 * k4 + 2), v3 = vmap(N, PH, 4 * k4 + 3);
            float ve = vt[v2], vo = vt[v3];
            vt[v2] = fmaf(ck, ve, -sk * vo);
            vt[v3] = fmaf(sk, ve,  ck * vo);
        }
    }
    // --- A migration: register side folds into SHFL source operands ---
    float tmp[N];
    #pragma unroll
    for (int i = 0; i < N; ++i) tmp[i] = a[sigma(N, i)];
    #pragma unroll
    for (int i = 0; i < N; ++i) a[i] = __shfl_sync(FULL, tmp[i], sig, W);
    if (PH) {   // restore vt with sigma^2 (two deferred migrations)
        float tv[N];
        #pragma unroll
        for (int i = 0; i < N; ++i) tv[i] = vt[sigma(N, sigma(N, i))];
        #pragma unroll
        for (int i = 0; i < N; ++i) vt[i] = tv[i];
    }
    dg = __shfl_sync(FULL, dg, sig, W);
}

template <int N, int W>
__device__ __forceinline__ void jacobi_smem(float* a, float* vt, float& dg,
                                            int llane, int sig, int iters,
                                            float* rb) {
    const int role = llane & 1;
    const int myk = llane >> 1;
    const int kk = (myk < N / 2) ? myk : 0;
    #pragma unroll 1
    for (int it = 0; it < iters; ++it) {
        jround<N, W, 0>(a, vt, dg, llane, sig, role, myk, kk, rb);
        jround<N, W, 1>(a, vt, dg, llane, sig, role, myk, kk, rb);
    }
}

__global__ __launch_bounds__(WPB * 32, 7)
void spdnet_kernel(const float* __restrict__ Xg,
                   const float* __restrict__ W1g,
                   const float* __restrict__ W2g,
                   float* __restrict__ out, int nb) {
    __shared__ float W1s[D1 * IN_DIM];           // 20x30
    __shared__ float W2s[D2 * D1];               // 15x20
    __shared__ __align__(16) float scr_all[WPB][SCRN];

    int tid = threadIdx.x, warp = tid >> 5, lane = tid & 31;
    for (int i = tid; i < D1 * IN_DIM; i += WPB * 32) W1s[i] = W1g[i];
    for (int i = tid; i < D2 * D1;    i += WPB * 32) W2s[i] = W2g[i];
    __syncthreads();

    int npairs = (nb + 1) >> 1;
    int wm = blockIdx.x * WPB + warp;
    if (wm >= npairs) return;      // warp-uniform; only warp-level sync below
    float* scr = scr_all[warp];

    // ============ stage 1 twice; park A2 columns (+diag) at scr[960+] =====
    #pragma unroll 1
    for (int h = 0; h < 2; ++h) {
        int m = 2 * wm + h; if (m >= nb) m = nb - 1;

        // ---- load X raw (pitch 32) + zero pad cols 30,31 (NO symmetrize) --
        {
            const float* xg = Xg + (size_t)m * 900;
            for (int e = lane; e < 900; e += 32) {
                int i = e / 30, k = e - i * 30;
                scr[i * 32 + k] = xg[e];
            }
            for (int e = lane; e < 60; e += 32)
                scr[(e >> 1) * 32 + 30 + (e & 1)] = 0.0f;
        }
        __syncwarp();

        // ---- bimap1 raw: araw[r] = w1_r . X . w1_lane (column per lane) --
        float a[D1], vt[D1], dg = 1.0f;
        #pragma unroll
        for (int i = 0; i < D1; ++i) { a[i] = 0.0f; vt[i] = 0.0f; }
        if (lane < D1) {
            float wreg[32];
            #pragma unroll
            for (int k = 0; k < IN_DIM; ++k) wreg[k] = W1s[lane * IN_DIM + k];
            wreg[30] = 0.0f; wreg[31] = 0.0f;
            float t[IN_DIM];
            for (int i = 0; i < IN_DIM; ++i) {
                const float4* x4 = reinterpret_cast<const float4*>(&scr[i * 32]);
                float acc = 0.0f;
                #pragma unroll
                for (int q = 0; q < 8; ++q) {
                    float4 x = x4[q];
                    acc = fmaf(x.x, wreg[4 * q + 0], acc);
                    acc = fmaf(x.y, wreg[4 * q + 1], acc);
                    acc = fmaf(x.z, wreg[4 * q + 2], acc);
                    acc = fmaf(x.w, wreg[4 * q + 3], acc);
                }
                t[i] = acc;
            }
            #pragma unroll
            for (int r = 0; r < D1; ++r) {
                float acc = 0.0f;
                #pragma unroll
                for (int i = 0; i < IN_DIM; ++i)
                    acc = fmaf(W1s[r * IN_DIM + i], t[i], acc);
                a[r] = acc;
            }
        }
        __syncwarp();   // all X reads complete before scr reuse

        // ---- symmetrize A via smem transpose: A = (Araw + Araw^T)/2 ------
        if (lane < D1) {
            #pragma unroll
            for (int k = 0; k < D1; ++k) scr[lane * 21 + k] = a[k];
        }
        __syncwarp();
        if (lane < D1) {
            #pragma unroll
            for (int k = 0; k < D1; ++k) {
                a[k] = 0.5f * (a[k] + scr[k * 21 + lane]);
                if (k == lane) { a[k] += EPS; dg = a[k]; }
            }
            #pragma unroll
            for (int k = 0; k < D1; ++k) vt[k] = (k == lane) ? 1.0f : 0.0f;
        }
        __syncwarp();

        // ---- eigensolve 20x20 (rb at scr+896) ----
        jacobi_smem<D1, 32>(a, vt, dg, lane, sigma(D1, lane), IT1, scr + 896);

        // ---- fused reeig + bimap2: A2 = Z Z^T + EPS*I, Z = W2*(V*sqrt) ----
        float g = sqrtf(fmaxf(dg, EPS));
        #pragma unroll
        for (int k = 0; k < D1; ++k) {
            float rk = __shfl_sync(FULL, g, k);
            vt[k] *= rk;
        }
        if (lane < D1) {
            #pragma unroll
            for (int k = 0; k < D1; ++k) scr[lane * 24 + k] = vt[k]; // Vs p24
        }
        __syncwarp();
        float z[D1];
        #pragma unroll
        for (int k = 0; k < D1; ++k) z[k] = 0.0f;
        if (lane < D2) {
            float w2r[D1];
            #pragma unroll
            for (int r = 0; r < D1; ++r) w2r[r] = W2s[lane * D1 + r];
            for (int r = 0; r < D1; ++r) {
                const float4* v4 = reinterpret_cast<const float4*>(&scr[r * 24]);
                float w = w2r[r];
                #pragma unroll
                for (int q = 0; q < 5; ++q) {
                    float4 x = v4[q];
                    z[4 * q + 0] = fmaf(w, x.x, z[4 * q + 0]);
                    z[4 * q + 1] = fmaf(w, x.y, z[4 * q + 1]);
                    z[4 * q + 2] = fmaf(w, x.z, z[4 * q + 2]);
                    z[4 * q + 3] = fmaf(w, x.w, z[4 * q + 3]);
                }
            }
        }
        __syncwarp();
        if (lane < D2) {
            #pragma unroll
            for (int k = 0; k < D1; ++k) scr[480 + lane * 24 + k] = z[k]; // Zs
        }
        __syncwarp();

        if (lane < 16) {
            float a2[16];
            #pragma unroll
            for (int b = 0; b < D2; ++b) {        // A2[b][lane] = Zrow_b . z
                const float4* zb = reinterpret_cast<const float4*>(&scr[480 + b * 24]);
                float acc = 0.0f;
                #pragma unroll
                for (int q = 0; q < 5; ++q) {
                    float4 x = zb[q];
                    acc = fmaf(x.x, z[4 * q + 0], acc);
                    acc = fmaf(x.y, z[4 * q + 1], acc);
                    acc = fmaf(x.z, z[4 * q + 2], acc);
                    acc = fmaf(x.w, z[4 * q + 3], acc);
                }
                a2[b] = acc;
            }
            a2[15] = 0.0f;                        // padded dim decoupled
            a2[lane] += EPS;
            float4* dst = reinterpret_cast<float4*>(&scr[960 + h * 272 + lane * 16]);
            const float4* src = reinterpret_cast<const float4*>(a2);
            #pragma unroll
            for (int q = 0; q < 4; ++q) dst[q] = src[q];
            scr[960 + h * 272 + 256 + lane] = a2[lane];
        }
        __syncwarp();
    }

    // ====== dual 16x16 eigensolve: lanes 0-15 mat 0, lanes 16-31 mat 1 =====
    int g2 = lane >> 4, llane = lane & 15;
    float A2[16], vt2[16];
    {
        const float4* src = reinterpret_cast<const float4*>(&scr[960 + g2 * 272 + llane * 16]);
        float4* dst = reinterpret_cast<float4*>(A2);
        #pragma unroll
        for (int q = 0; q < 4; ++q) dst[q] = src[q];
    }
    float dg2 = scr[960 + g2 * 272 + 256 + llane];
    #pragma unroll
    for (int k = 0; k < 16; ++k) vt2[k] = (k == llane) ? 1.0f : 0.0f;
    __syncwarp();

    // rb for the two groups at scr[0..96) (Vs/Zs dead)
    jacobi_smem<16, 16>(A2, vt2, dg2, llane, sigma(16, llane), IT2,
                        scr + g2 * 48);

    // ============== logeig recompose (per group), triangle output =========
    float lw = logf(fmaxf(dg2, EPS));
    __syncwarp();   // rb reads done before recompose overwrites scr[0..96)
    #pragma unroll
    for (int k = 0; k < 16; ++k) {
        float lwk = __shfl_sync(FULL, lw, k, 16);
        float raw = vt2[k];
        if (llane < D2) {
            scr[g2 * 512 + llane * 16 + k]       = raw;        // raw rows
            scr[g2 * 512 + 256 + llane * 16 + k] = raw * lwk;  // scaled rows
        }
    }
    __syncwarp();

    int m = 2 * wm + g2;
    if (m < nb) {
        const float* base = &scr[g2 * 512];
        for (int tt = llane; tt < 120; tt += 16) {
            // closed-form (i,j): row boundaries are exact squares (2i-31)^2
            int i = (int)((31.0f - sqrtf(961.0f - 8.0f * (float)tt)) * 0.5f);
            int j = tt - ((i * (31 - i)) >> 1) + i;
            const float4* ri = reinterpret_cast<const float4*>(&base[256 + i * 16]);
            const float4* rj = reinterpret_cast<const float4*>(&base[j * 16]);
            float acc = 0.0f;
            #pragma unroll
            for (int q = 0; q < 4; ++q) {
                float4 x = ri[q], y = rj[q];
                acc = fmaf(x.x, y.x, fmaf(x.y, y.y, fmaf(x.z, y.z, fmaf(x.w, y.w, acc))));
            }
            out[(size_t)m * 120 + tt] = acc;
        }
    }
}

extern "C" void kernel_launch(void* const* d_in, const int* in_sizes, int n_in,
                              void* d_out, int out_size) {
    const float* X  = (const float*)d_in[0];
    const float* W1 = (const float*)d_in[1];
    const float* W2 = (const float*)d_in[2];
    float* out = (float*)d_out;
    int nb = in_sizes[0] / (IN_DIM * IN_DIM);
    int npairs = (nb + 1) / 2;
    int blocks = (npairs + WPB - 1) / WPB;
    spdnet_kernel<<<blocks, WPB * 32>>>(X, W1, W2, out, nb);
}

// round 16
// speedup vs baseline: 1.7658x; 1.0307x over previous
#include <cuda_runtime.h>

#define EPS 1e-4f
constexpr int IN_DIM = 30;
constexpr int D1 = 20;
constexpr int D2 = 15;
constexpr int WPB = 4;          // warps per block; each warp: 2 matrices
constexpr int IT1 = 46;         // 92 rounds (~4.8 sweeps of 20x20)
constexpr int IT2 = 37;         // 74 rounds (~4.9 sweeps of 16x16)
constexpr int SCRN = 1536;      // floats of scratch per warp
constexpr unsigned FULL = 0xffffffffu;

// Tournament migration: NEW[l] = OLD[sigma(l)]. Position 0 fixed.
__host__ __device__ constexpr int sigma(int N, int l) {
    if (l >= N) return l;
    if (l == 0) return 0;
    if (l == N - 1) return N - 2;
    if (l & 1) return l + 2;   // odd slots move down the ring
    if (l == 2) return 1;
    return l - 2;              // even slots >= 4
}

// vt register index for phase PH (0: canonical, 1: one migration deferred)
__host__ __device__ constexpr int vmap(int N, int PH, int i) {
    return PH ? sigma(N, i) : i;
}

// One Jacobi round. A registers stay canonical (migrated every round,
// register side folds into the SHFL). vt migration is DEFERRED on PH=0
// rounds; PH=1 rounds address vt through sigma and then restore with a
// single sigma^2 permutation. rb: cs[2][N/2 float2] at 0, diag[2][N/2]
// at 2N (double-buffered by PH).
template <int N, int W, int PH>
__device__ __forceinline__ void jround(float* a, float* vt, float& dg,
                                       int llane, int sig, int role,
                                       int myk, int kk, float* rb) {
    constexpr int buf = PH;
    float d_oth = __shfl_xor_sync(FULL, dg, 1);
    // --- even pair-lane computes rotation, publishes via shared ---
    if (!role && llane < N) {
        float off = 0.0f;
        #pragma unroll
        for (int k = 0; k < N / 2; ++k)
            if (myk == k) off = a[2 * k + 1];   // off-diag A[q][p]
        float c = 1.0f, s = 0.0f, t = 0.0f;
        if (fabsf(off) > 1e-30f) {
            float tau = (d_oth - dg) / (2.0f * off);
            t = copysignf(1.0f, tau) /
                (fabsf(tau) + sqrtf(fmaf(tau, tau, 1.0f)));
            c = rsqrtf(fmaf(t, t, 1.0f));
            s = t * c;
        }
        reinterpret_cast<float2*>(rb + buf * N)[myk] = make_float2(c, s);
        rb[2 * N + buf * (N / 2) + myk] = fmaf(t, off, d_oth); // odd diag'
        dg = fmaf(-t, off, dg);                                // even diag'
    }
    __syncwarp();
    // --- own-pair coefficients (LDS.64; broadcast within pair) ---
    float2 mycs = reinterpret_cast<const float2*>(rb + buf * N)[kk];
    float c = mycs.x, s = mycs.y;
    if (role) dg = rb[2 * N + buf * (N / 2) + kk];
    // --- column phase: A <- A*J (partner exchange via shfl_xor) ---
    float sg = role ? s : -s;
    #pragma unroll
    for (int i = 0; i < N; ++i) {
        float o = __shfl_xor_sync(FULL, a[i], 1);
        a[i] = fmaf(c, a[i], sg * o);
    }
    // --- row phase: A canonical indices; vt via vmap; cs via LDS.128 ---
    const float4* csv = reinterpret_cast<const float4*>(rb + buf * N);
    #pragma unroll
    for (int k4 = 0; k4 < N / 4; ++k4) {
        float4 q = csv[k4];
        {
            float ck = q.x, sk = q.y;
            float ae = a[4 * k4], ao = a[4 * k4 + 1];
            a[4 * k4]     = fmaf(ck, ae, -sk * ao);
            a[4 * k4 + 1] = fmaf(sk, ae,  ck * ao);
            const int v0 = vmap(N, PH, 4 * k4), v1 = vmap(N, PH, 4 * k4 + 1);
            float ve = vt[v0], vo = vt[v1];
            vt[v0] = fmaf(ck, ve, -sk * vo);
            vt[v1] = fmaf(sk, ve,  ck * vo);
        }
        {
            float ck = q.z, sk = q.w;
            float ae = a[4 * k4 + 2], ao = a[4 * k4 + 3];
            a[4 * k4 + 2] = fmaf(ck, ae, -sk * ao);
            a[4 * k4 + 3] = fmaf(sk, ae,  ck * ao);
            const int v2 = vmap(N, PH, 4 * k4 + 2), v3 = vmap(N, PH, 4 * k4 + 3);
            float ve = vt[v2], vo = vt[v3];
            vt[v2] = fmaf(ck, ve, -sk * vo);
            vt[v3] = fmaf(sk, ve,  ck * vo);
        }
    }
    // --- A migration: register side folds into SHFL source operands ---
    float tmp[N];
    #pragma unroll
    for (int i = 0; i < N; ++i) tmp[i] = a[sigma(N, i)];
    #pragma unroll
    for (int i = 0; i < N; ++i) a[i] = __shfl_sync(FULL, tmp[i], sig, W);
    if (PH) {   // restore vt with sigma^2 (two deferred migrations)
        float tv[N];
        #pragma unroll
        for (int i = 0; i < N; ++i) tv[i] = vt[sigma(N, sigma(N, i))];
        #pragma unroll
        for (int i = 0; i < N; ++i) vt[i] = tv[i];
    }
    dg = __shfl_sync(FULL, dg, sig, W);
}

template <int N, int W>
__device__ __forceinline__ void jacobi_smem(float* a, float* vt, float& dg,
                                            int llane, int sig, int iters,
                                            float* rb) {
    const int role = llane & 1;
    const int myk = llane >> 1;
    const int kk = (myk < N / 2) ? myk : 0;
    #pragma unroll 1
    for (int it = 0; it < iters; ++it) {
        jround<N, W, 0>(a, vt, dg, llane, sig, role, myk, kk, rb);
        jround<N, W, 1>(a, vt, dg, llane, sig, role, myk, kk, rb);
    }
}

__global__ __launch_bounds__(WPB * 32, 7)
void spdnet_kernel(const float* __restrict__ Xg,
                   const float* __restrict__ W1g,
                   const float* __restrict__ W2g,
                   float* __restrict__ out, int nb) {
    __shared__ float W1s[D1 * IN_DIM];           // 20x30
    __shared__ float W2s[D2 * D1];               // 15x20
    __shared__ __align__(16) float scr_all[WPB][SCRN];

    int tid = threadIdx.x, warp = tid >> 5, lane = tid & 31;
    for (int i = tid; i < D1 * IN_DIM; i += WPB * 32) W1s[i] = W1g[i];
    for (int i = tid; i < D2 * D1;    i += WPB * 32) W2s[i] = W2g[i];
    __syncthreads();

    int npairs = (nb + 1) >> 1;
    int wm = blockIdx.x * WPB + warp;
    if (wm >= npairs) return;      // warp-uniform; only warp-level sync below
    float* scr = scr_all[warp];

    // ============ stage 1 twice; park A2 columns (+diag) at scr[960+] =====
    #pragma unroll 1
    for (int h = 0; h < 2; ++h) {
        int m = 2 * wm + h; if (m >= nb) m = nb - 1;

        // ---- load X raw (pitch 32) + zero pad cols 30,31 (NO symmetrize) --
        {
            const float* xg = Xg + (size_t)m * 900;
            for (int e = lane; e < 900; e += 32) {
                int i = e / 30, k = e - i * 30;
                scr[i * 32 + k] = xg[e];
            }
            for (int e = lane; e < 60; e += 32)
                scr[(e >> 1) * 32 + 30 + (e & 1)] = 0.0f;
        }
        __syncwarp();

        // ---- bimap1 raw: araw[r] = w1_r . X . w1_lane (column per lane) --
        float a[D1], vt[D1], dg = 1.0f;
        #pragma unroll
        for (int i = 0; i < D1; ++i) { a[i] = 0.0f; vt[i] = 0.0f; }
        if (lane < D1) {
            float wreg[32];
            #pragma unroll
            for (int k = 0; k < IN_DIM; ++k) wreg[k] = W1s[lane * IN_DIM + k];
            wreg[30] = 0.0f; wreg[31] = 0.0f;
            float t[IN_DIM];
            for (int i = 0; i < IN_DIM; ++i) {
                const float4* x4 = reinterpret_cast<const float4*>(&scr[i * 32]);
                float acc = 0.0f;
                #pragma unroll
                for (int q = 0; q < 8; ++q) {
                    float4 x = x4[q];
                    acc = fmaf(x.x, wreg[4 * q + 0], acc);
                    acc = fmaf(x.y, wreg[4 * q + 1], acc);
                    acc = fmaf(x.z, wreg[4 * q + 2], acc);
                    acc = fmaf(x.w, wreg[4 * q + 3], acc);
                }
                t[i] = acc;
            }
            #pragma unroll
            for (int r = 0; r < D1; ++r) {
                float acc = 0.0f;
                #pragma unroll
                for (int i = 0; i < IN_DIM; ++i)
                    acc = fmaf(W1s[r * IN_DIM + i], t[i], acc);
                a[r] = acc;
            }
        }
        __syncwarp();   // all X reads complete before scr reuse

        // ---- symmetrize A via smem transpose: A = (Araw + Araw^T)/2 ------
        if (lane < D1) {
            #pragma unroll
            for (int k = 0; k < D1; ++k) scr[lane * 21 + k] = a[k];
        }
        __syncwarp();
        if (lane < D1) {
            #pragma unroll
            for (int k = 0; k < D1; ++k) {
                a[k] = 0.5f * (a[k] + scr[k * 21 + lane]);
                if (k == lane) { a[k] += EPS; dg = a[k]; }
            }
            #pragma unroll
            for (int k = 0; k < D1; ++k) vt[k] = (k == lane) ? 1.0f : 0.0f;
        }
        __syncwarp();

        // ---- eigensolve 20x20 (rb at scr+896) ----
        jacobi_smem<D1, 32>(a, vt, dg, lane, sigma(D1, lane), IT1, scr + 896);

        // ---- fused reeig + bimap2: A2 = Z Z^T + EPS*I, Z = W2*(V*sqrt) ----
        float g = sqrtf(fmaxf(dg, EPS));
        #pragma unroll
        for (int k = 0; k < D1; ++k) {
            float rk = __shfl_sync(FULL, g, k);
            vt[k] *= rk;
        }
        if (lane < D1) {
            #pragma unroll
            for (int k = 0; k < D1; ++k) scr[lane * 24 + k] = vt[k]; // Vs p24
        }
        __syncwarp();
        float z[D1];
        #pragma unroll
        for (int k = 0; k < D1; ++k) z[k] = 0.0f;
        if (lane < D2) {
            float w2r[D1];
            #pragma unroll
            for (int r = 0; r < D1; ++r) w2r[r] = W2s[lane * D1 + r];
            for (int r = 0; r < D1; ++r) {
                const float4* v4 = reinterpret_cast<const float4*>(&scr[r * 24]);
                float w = w2r[r];
                #pragma unroll
                for (int q = 0; q < 5; ++q) {
                    float4 x = v4[q];
                    z[4 * q + 0] = fmaf(w, x.x, z[4 * q + 0]);
                    z[4 * q + 1] = fmaf(w, x.y, z[4 * q + 1]);
                    z[4 * q + 2] = fmaf(w, x.z, z[4 * q + 2]);
                    z[4 * q + 3] = fmaf(w, x.w, z[4 * q + 3]);
                }
            }
        }
        __syncwarp();
        if (lane < D2) {
            #pragma unroll
            for (int k = 0; k < D1; ++k) scr[480 + lane * 24 + k] = z[k]; // Zs
        }
        __syncwarp();

        if (lane < 16) {
            float a2[16];
            #pragma unroll
            for (int b = 0; b < D2; ++b) {        // A2[b][lane] = Zrow_b . z
                const float4* zb = reinterpret_cast<const float4*>(&scr[480 + b * 24]);
                float acc = 0.0f;
                #pragma unroll
                for (int q = 0; q < 5; ++q) {
                    float4 x = zb[q];
                    acc = fmaf(x.x, z[4 * q + 0], acc);
                    acc = fmaf(x.y, z[4 * q + 1], acc);
                    acc = fmaf(x.z, z[4 * q + 2], acc);
                    acc = fmaf(x.w, z[4 * q + 3], acc);
                }
                a2[b] = acc;
            }
            a2[15] = 0.0f;                        // padded dim decoupled
            a2[lane] += EPS;
            float4* dst = reinterpret_cast<float4*>(&scr[960 + h * 272 + lane * 16]);
            const float4* src = reinterpret_cast<const float4*>(a2);
            #pragma unroll
            for (int q = 0; q < 4; ++q) dst[q] = src[q];
            scr[960 + h * 272 + 256 + lane] = a2[lane];
        }
        __syncwarp();
    }

    // ====== dual 16x16 eigensolve: lanes 0-15 mat 0, lanes 16-31 mat 1 =====
    int g2 = lane >> 4, llane = lane & 15;
    float A2[16], vt2[16];
    {
        const float4* src = reinterpret_cast<const float4*>(&scr[960 + g2 * 272 + llane * 16]);
        float4* dst = reinterpret_cast<float4*>(A2);
        #pragma unroll
        for (int q = 0; q < 4; ++q) dst[q] = src[q];
    }
    float dg2 = scr[960 + g2 * 272 + 256 + llane];
    #pragma unroll
    for (int k = 0; k < 16; ++k) vt2[k] = (k == llane) ? 1.0f : 0.0f;
    __syncwarp();

    // rb for the two groups at scr[0..96) (Vs/Zs dead)
    jacobi_smem<16, 16>(A2, vt2, dg2, llane, sigma(16, llane), IT2,
                        scr + g2 * 48);

    // ============== logeig recompose (per group), triangle output =========
    float lw = logf(fmaxf(dg2, EPS));
    __syncwarp();   // rb reads done before recompose overwrites scr[0..96)
    #pragma unroll
    for (int k = 0; k < 16; ++k) {
        float lwk = __shfl_sync(FULL, lw, k, 16);
        float raw = vt2[k];
        if (llane < D2) {
            scr[g2 * 512 + llane * 16 + k]       = raw;        // raw rows
            scr[g2 * 512 + 256 + llane * 16 + k] = raw * lwk;  // scaled rows
        }
    }
    __syncwarp();

    int m = 2 * wm + g2;
    if (m < nb) {
        const float* base = &scr[g2 * 512];
        for (int tt = llane; tt < 120; tt += 16) {
            // closed-form (i,j): row boundaries are exact squares (2i-31)^2
            int i = (int)((31.0f - sqrtf(961.0f - 8.0f * (float)tt)) * 0.5f);
            int j = tt - ((i * (31 - i)) >> 1) + i;
            const float4* ri = reinterpret_cast<const float4*>(&base[256 + i * 16]);
            const float4* rj = reinterpret_cast<const float4*>(&base[j * 16]);
            float acc = 0.0f;
            #pragma unroll
            for (int q = 0; q < 4; ++q) {
                float4 x = ri[q], y = rj[q];
                acc = fmaf(x.x, y.x, fmaf(x.y, y.y, fmaf(x.z, y.z, fmaf(x.w, y.w, acc))));
            }
            out[(size_t)m * 120 + tt] = acc;
        }
    }
}

extern "C" void kernel_launch(void* const* d_in, const int* in_sizes, int n_in,
                              void* d_out, int out_size) {
    const float* X  = (const float*)d_in[0];
    const float* W1 = (const float*)d_in[1];
    const float* W2 = (const float*)d_in[2];
    float* out = (float*)d_out;
    int nb = in_sizes[0] / (IN_DIM * IN_DIM);
    int npairs = (nb + 1) / 2;
    int blocks = (npairs + WPB - 1) / WPB;
    spdnet_kernel<<<blocks, WPB * 32>>>(X, W1, W2, out, nb);
}

// round 17
// speedup vs baseline: 1.8084x; 1.0241x over previous
#include <cuda_runtime.h>

#define EPS 1e-4f
constexpr int IN_DIM = 30;
constexpr int D1 = 20;
constexpr int D2 = 15;
constexpr int WPB = 4;          // warps per block; each warp: 2 matrices
constexpr int IT1 = 46;         // 92 rounds (~4.8 sweeps of 20x20)
constexpr int IT2 = 37;         // 74 rounds (~4.9 sweeps of 16x16)
constexpr int SCRN = 1536;      // floats of scratch per warp
constexpr unsigned FULL = 0xffffffffu;

// packed f32x2 helpers (FFMA2 is PTX-only; see SASS_QUICKREF)
#define FMA2(acc, va, vb) \
    asm("fma.rn.f32x2 %0, %1, %2, %0;" : "+l"(acc) : "l"(va), "l"(vb))
#define PACK2(out, lo, hi) \
    asm("mov.b64 %0, {%1, %2};" : "=l"(out) : "r"(__float_as_uint(lo)), "r"(__float_as_uint(hi)))
#define UNPACK2(lo, hi, in) \
    asm("mov.b64 {%0, %1}, %2;" : "=f"(lo), "=f"(hi) : "l"(in))

// Tournament migration: NEW[l] = OLD[sigma(l)]. Position 0 fixed.
__host__ __device__ constexpr int sigma(int N, int l) {
    if (l >= N) return l;
    if (l == 0) return 0;
    if (l == N - 1) return N - 2;
    if (l & 1) return l + 2;   // odd slots move down the ring
    if (l == 2) return 1;
    return l - 2;              // even slots >= 4
}

// vt register index for phase PH (0: canonical, 1: one migration deferred)
__host__ __device__ constexpr int vmap(int N, int PH, int i) {
    return PH ? sigma(N, i) : i;
}

// One Jacobi round. A registers stay canonical (migrated every round,
// register side folds into the SHFL). vt migration is DEFERRED on PH=0
// rounds; PH=1 rounds address vt through sigma and then restore with a
// single sigma^2 permutation. rb: cs[2][N/2 float2] at 0, diag[2][N/2]
// at 2N (double-buffered by PH).
template <int N, int W, int PH>
__device__ __forceinline__ void jround(float* a, float* vt, float& dg,
                                       int llane, int sig, int role,
                                       int myk, int kk, float* rb) {
    constexpr int buf = PH;
    float d_oth = __shfl_xor_sync(FULL, dg, 1);
    // --- even pair-lane computes rotation, publishes via shared ---
    if (!role && llane < N) {
        float off = 0.0f;
        #pragma unroll
        for (int k = 0; k < N / 2; ++k)
            if (myk == k) off = a[2 * k + 1];   // off-diag A[q][p]
        float c = 1.0f, s = 0.0f, t = 0.0f;
        if (fabsf(off) > 1e-30f) {
            float tau = (d_oth - dg) / (2.0f * off);
            t = copysignf(1.0f, tau) /
                (fabsf(tau) + sqrtf(fmaf(tau, tau, 1.0f)));
            c = rsqrtf(fmaf(t, t, 1.0f));
            s = t * c;
        }
        reinterpret_cast<float2*>(rb + buf * N)[myk] = make_float2(c, s);
        rb[2 * N + buf * (N / 2) + myk] = fmaf(t, off, d_oth); // odd diag'
        dg = fmaf(-t, off, dg);                                // even diag'
    }
    __syncwarp();
    // --- own-pair coefficients (LDS.64; broadcast within pair) ---
    float2 mycs = reinterpret_cast<const float2*>(rb + buf * N)[kk];
    float c = mycs.x, s = mycs.y;
    if (role) dg = rb[2 * N + buf * (N / 2) + kk];
    // --- column phase: A <- A*J (partner exchange via shfl_xor) ---
    float sg = role ? s : -s;
    #pragma unroll
    for (int i = 0; i < N; ++i) {
        float o = __shfl_xor_sync(FULL, a[i], 1);
        a[i] = fmaf(c, a[i], sg * o);
    }
    // --- row phase: A canonical indices; vt via vmap; cs via LDS.128 ---
    const float4* csv = reinterpret_cast<const float4*>(rb + buf * N);
    #pragma unroll
    for (int k4 = 0; k4 < N / 4; ++k4) {
        float4 q = csv[k4];
        {
            float ck = q.x, sk = q.y;
            float ae = a[4 * k4], ao = a[4 * k4 + 1];
            a[4 * k4]     = fmaf(ck, ae, -sk * ao);
            a[4 * k4 + 1] = fmaf(sk, ae,  ck * ao);
            const int v0 = vmap(N, PH, 4 * k4), v1 = vmap(N, PH, 4 * k4 + 1);
            float ve = vt[v0], vo = vt[v1];
            vt[v0] = fmaf(ck, ve, -sk * vo);
            vt[v1] = fmaf(sk, ve,  ck * vo);
        }
        {
            float ck = q.z, sk = q.w;
            float ae = a[4 * k4 + 2], ao = a[4 * k4 + 3];
            a[4 * k4 + 2] = fmaf(ck, ae, -sk * ao);
            a[4 * k4 + 3] = fmaf(sk, ae,  ck * ao);
            const int v2 = vmap(N, PH, 4 * k4 + 2), v3 = vmap(N, PH, 4 * k4 + 3);
            float ve = vt[v2], vo = vt[v3];
            vt[v2] = fmaf(ck, ve, -sk * vo);
            vt[v3] = fmaf(sk, ve,  ck * vo);
        }
    }
    // --- A migration: register side folds into SHFL source operands ---
    float tmp[N];
    #pragma unroll
    for (int i = 0; i < N; ++i) tmp[i] = a[sigma(N, i)];
    #pragma unroll
    for (int i = 0; i < N; ++i) a[i] = __shfl_sync(FULL, tmp[i], sig, W);
    if (PH) {   // restore vt with sigma^2 (two deferred migrations)
        float tv[N];
        #pragma unroll
        for (int i = 0; i < N; ++i) tv[i] = vt[sigma(N, sigma(N, i))];
        #pragma unroll
        for (int i = 0; i < N; ++i) vt[i] = tv[i];
    }
    dg = __shfl_sync(FULL, dg, sig, W);
}

template <int N, int W>
__device__ __forceinline__ void jacobi_smem(float* a, float* vt, float& dg,
                                            int llane, int sig, int iters,
                                            float* rb) {
    const int role = llane & 1;
    const int myk = llane >> 1;
    const int kk = (myk < N / 2) ? myk : 0;
    #pragma unroll 1
    for (int it = 0; it < iters; ++it) {
        jround<N, W, 0>(a, vt, dg, llane, sig, role, myk, kk, rb);
        jround<N, W, 1>(a, vt, dg, llane, sig, role, myk, kk, rb);
    }
}

__global__ __launch_bounds__(WPB * 32, 7)
void spdnet_kernel(const float* __restrict__ Xg,
                   const float* __restrict__ W1g,
                   const float* __restrict__ W2g,
                   float* __restrict__ out, int nb) {
    __shared__ float W1s[D1 * IN_DIM];           // 20x30
    __shared__ float W2s[D2 * D1];               // 15x20
    __shared__ __align__(16) float scr_all[WPB][SCRN];

    int tid = threadIdx.x, warp = tid >> 5, lane = tid & 31;
    for (int i = tid; i < D1 * IN_DIM; i += WPB * 32) W1s[i] = W1g[i];
    for (int i = tid; i < D2 * D1;    i += WPB * 32) W2s[i] = W2g[i];
    __syncthreads();

    int npairs = (nb + 1) >> 1;
    int wm = blockIdx.x * WPB + warp;
    if (wm >= npairs) return;      // warp-uniform; only warp-level sync below
    float* scr = scr_all[warp];

    // ============ stage 1 twice; park A2 columns (+diag) at scr[960+] =====
    #pragma unroll 1
    for (int h = 0; h < 2; ++h) {
        int m = 2 * wm + h; if (m >= nb) m = nb - 1;

        // ---- load X raw (pitch 32) + zero pad cols 30,31 (NO symmetrize) --
        {
            const float* xg = Xg + (size_t)m * 900;
            for (int e = lane; e < 900; e += 32) {
                int i = e / 30, k = e - i * 30;
                scr[i * 32 + k] = xg[e];
            }
            for (int e = lane; e < 60; e += 32)
                scr[(e >> 1) * 32 + 30 + (e & 1)] = 0.0f;
        }
        __syncwarp();

        // ---- bimap1 raw (packed f32x2): araw[r] = w1_r . X . w1_lane -----
        float a[D1], vt[D1], dg = 1.0f;
        #pragma unroll
        for (int i = 0; i < D1; ++i) { a[i] = 0.0f; vt[i] = 0.0f; }
        if (lane < D1) {
            unsigned long long wp[16];
            #pragma unroll
            for (int k = 0; k < 15; ++k)     // 120*lane bytes: 8B aligned
                wp[k] = *reinterpret_cast<const unsigned long long*>(
                            &W1s[lane * IN_DIM + 2 * k]);
            wp[15] = 0ull;                   // covers zero pad cols 30,31
            float t[IN_DIM];
            for (int i = 0; i < IN_DIM; ++i) {     // t = X^T-row dot w1_lane
                const ulonglong2* x4 =
                    reinterpret_cast<const ulonglong2*>(&scr[i * 32]);
                unsigned long long acc2 = 0ull;
                #pragma unroll
                for (int q = 0; q < 8; ++q) {
                    ulonglong2 xx = x4[q];
                    FMA2(acc2, xx.x, wp[2 * q]);
                    FMA2(acc2, xx.y, wp[2 * q + 1]);
                }
                float lo, hi; UNPACK2(lo, hi, acc2);
                t[i] = lo + hi;
            }
            unsigned long long tp[15];
            #pragma unroll
            for (int k = 0; k < 15; ++k) PACK2(tp[k], t[2 * k], t[2 * k + 1]);
            #pragma unroll
            for (int r = 0; r < D1; ++r) {         // a[r] = w1_r . t
                const unsigned long long* w2 =
                    reinterpret_cast<const unsigned long long*>(&W1s[r * IN_DIM]);
                unsigned long long acc2 = 0ull;
                #pragma unroll
                for (int k = 0; k < 15; ++k) FMA2(acc2, w2[k], tp[k]);
                float lo, hi; UNPACK2(lo, hi, acc2);
                a[r] = lo + hi;
            }
        }
        __syncwarp();   // all X reads complete before scr reuse

        // ---- symmetrize A via smem transpose: A = (Araw + Araw^T)/2 ------
        if (lane < D1) {
            #pragma unroll
            for (int k = 0; k < D1; ++k) scr[lane * 21 + k] = a[k];
        }
        __syncwarp();
        if (lane < D1) {
            #pragma unroll
            for (int k = 0; k < D1; ++k) {
                a[k] = 0.5f * (a[k] + scr[k * 21 + lane]);
                if (k == lane) { a[k] += EPS; dg = a[k]; }
            }
            #pragma unroll
            for (int k = 0; k < D1; ++k) vt[k] = (k == lane) ? 1.0f : 0.0f;
        }
        __syncwarp();

        // ---- eigensolve 20x20 (rb at scr+896) ----
        jacobi_smem<D1, 32>(a, vt, dg, lane, sigma(D1, lane), IT1, scr + 896);

        // ---- fused reeig + bimap2: A2 = Z Z^T + EPS*I, Z = W2*(V*sqrt) ----
        float g = sqrtf(fmaxf(dg, EPS));
        #pragma unroll
        for (int k = 0; k < D1; ++k) {
            float rk = __shfl_sync(FULL, g, k);
            vt[k] *= rk;
        }
        if (lane < D1) {
            #pragma unroll
            for (int k = 0; k < D1; ++k) scr[lane * 24 + k] = vt[k]; // Vs p24
        }
        __syncwarp();
        unsigned long long zp[10];                  // z packed (f32x2)
        #pragma unroll
        for (int k = 0; k < 10; ++k) zp[k] = 0ull;
        if (lane < D2) {
            float w2r[D1];
            #pragma unroll
            for (int r = 0; r < D1; ++r) w2r[r] = W2s[lane * D1 + r];
            for (int r = 0; r < D1; ++r) {
                const ulonglong2* v4 =
                    reinterpret_cast<const ulonglong2*>(&scr[r * 24]);
                unsigned long long wpr;
                PACK2(wpr, w2r[r], w2r[r]);
                #pragma unroll
                for (int q = 0; q < 5; ++q) {
                    ulonglong2 vv = v4[q];
                    FMA2(zp[2 * q],     vv.x, wpr);
                    FMA2(zp[2 * q + 1], vv.y, wpr);
                }
            }
        }
        __syncwarp();
        if (lane < D2) {
            #pragma unroll                       // Zs packed stores (8B aligned)
            for (int k = 0; k < 10; ++k)
                *reinterpret_cast<unsigned long long*>(
                    &scr[480 + lane * 24 + 2 * k]) = zp[k];
        }
        __syncwarp();

        if (lane < 16) {
            float a2[16];
            #pragma unroll
            for (int b = 0; b < D2; ++b) {        // A2[b][lane] = Zrow_b . z
                const ulonglong2* zb =
                    reinterpret_cast<const ulonglong2*>(&scr[480 + b * 24]);
                unsigned long long acc2 = 0ull;
                #pragma unroll
                for (int q = 0; q < 5; ++q) {
                    ulonglong2 zz = zb[q];
                    FMA2(acc2, zz.x, zp[2 * q]);
                    FMA2(acc2, zz.y, zp[2 * q + 1]);
                }
                float lo, hi; UNPACK2(lo, hi, acc2);
                a2[b] = lo + hi;
            }
            a2[15] = 0.0f;                        // padded dim decoupled
            a2[lane] += EPS;
            float4* dst = reinterpret_cast<float4*>(&scr[960 + h * 272 + lane * 16]);
            const float4* src = reinterpret_cast<const float4*>(a2);
            #pragma unroll
            for (int q = 0; q < 4; ++q) dst[q] = src[q];
            scr[960 + h * 272 + 256 + lane] = a2[lane];
        }
        __syncwarp();
    }

    // ====== dual 16x16 eigensolve: lanes 0-15 mat 0, lanes 16-31 mat 1 =====
    int g2 = lane >> 4, llane = lane & 15;
    float A2[16], vt2[16];
    {
        const float4* src = reinterpret_cast<const float4*>(&scr[960 + g2 * 272 + llane * 16]);
        float4* dst = reinterpret_cast<float4*>(A2);
        #pragma unroll
        for (int q = 0; q < 4; ++q) dst[q] = src[q];
    }
    float dg2 = scr[960 + g2 * 272 + 256 + llane];
    #pragma unroll
    for (int k = 0; k < 16; ++k) vt2[k] = (k == llane) ? 1.0f : 0.0f;
    __syncwarp();

    // rb for the two groups at scr[0..96) (Vs/Zs dead)
    jacobi_smem<16, 16>(A2, vt2, dg2, llane, sigma(16, llane), IT2,
                        scr + g2 * 48);

    // ============== logeig recompose (per group), triangle output =========
    float lw = logf(fmaxf(dg2, EPS));
    __syncwarp();   // rb reads done before recompose overwrites scr[0..96)
    #pragma unroll
    for (int k = 0; k < 16; ++k) {
        float lwk = __shfl_sync(FULL, lw, k, 16);
        float raw = vt2[k];
        if (llane < D2) {
            scr[g2 * 512 + llane * 16 + k]       = raw;        // raw rows
            scr[g2 * 512 + 256 + llane * 16 + k] = raw * lwk;  // scaled rows
        }
    }
    __syncwarp();

    int m = 2 * wm + g2;
    if (m < nb) {
        const float* base = &scr[g2 * 512];
        for (int tt = llane; tt < 120; tt += 16) {
            // closed-form (i,j): row boundaries are exact squares (2i-31)^2
            int i = (int)((31.0f - sqrtf(961.0f - 8.0f * (float)tt)) * 0.5f);
            int j = tt - ((i * (31 - i)) >> 1) + i;
            const float4* ri = reinterpret_cast<const float4*>(&base[256 + i * 16]);
            const float4* rj = reinterpret_cast<const float4*>(&base[j * 16]);
            float acc = 0.0f;
            #pragma unroll
            for (int q = 0; q < 4; ++q) {
                float4 x = ri[q], y = rj[q];
                acc = fmaf(x.x, y.x, fmaf(x.y, y.y, fmaf(x.z, y.z, fmaf(x.w, y.w, acc))));
            }
            out[(size_t)m * 120 + tt] = acc;
        }
    }
}

extern "C" void kernel_launch(void* const* d_in, const int* in_sizes, int n_in,
                              void* d_out, int out_size) {
    const float* X  = (const float*)d_in[0];
    const float* W1 = (const float*)d_in[1];
    const float* W2 = (const float*)d_in[2];
    float* out = (float*)d_out;
    int nb = in_sizes[0] / (IN_DIM * IN_DIM);
    int npairs = (nb + 1) / 2;
    int blocks = (npairs + WPB - 1) / WPB;
    spdnet_kernel<<<blocks, WPB * 32>>>(X, W1, W2, out, nb);
}